// round 1
// baseline (speedup 1.0000x reference)
#include <cuda_runtime.h>
#include <math.h>

// ---------------------------------------------------------------------------
// Problem constants
// ---------------------------------------------------------------------------
namespace {
constexpr int Hh   = 16;
constexpr int Ww   = 21;
constexpr int HW   = Hh * Ww;        // 336
constexpr int CIN  = 256;
constexpr int COUT = 1024;           // 4*F
constexpr int Tt   = 16;
constexpr int Bb   = 4;
constexpr int Ff   = 256;

constexpr int KC      = 8;           // input-channel chunk
constexpr int CO_TILE = 64;          // output-channel tile per block
constexpr int PATCH   = 12;          // 8 + 4 halo
constexpr int PP      = PATCH * PATCH;  // 144
constexpr int PSTR    = 145;         // padded stride (bank-conflict free)
constexpr int NTAP    = 25;

constexpr int SMEM_FLOATS = KC * PSTR + NTAP * KC * CO_TILE;   // 1160 + 12800
constexpr int SMEM_BYTES  = SMEM_FLOATS * 4;                   // 55,840 B

constexpr size_t SEQ_ELEMS   = (size_t)Bb * Tt * HW * Ff;      // 5,505,024
constexpr size_t STATE_ELEMS = (size_t)Bb * HW * Ff;           // 344,064
constexpr size_t XG_ELEMS    = (size_t)Bb * Tt * HW * COUT;    // 22,020,096
}

// ---------------------------------------------------------------------------
// Scratch (device globals — no allocation allowed)
// ---------------------------------------------------------------------------
__device__ float  g_xg[XG_ELEMS];      // gate pre-activations (reused L1/L2)
__device__ float  g_seq1[SEQ_ELEMS];   // layer-1 hidden sequence
__device__ float  g_seq2[SEQ_ELEMS];   // layer-2 hidden sequence (pre-norm)
__device__ float  g_c[STATE_ELEMS];    // cell state (reused L1/L2)
__device__ float2 g_stats[Bb * Ff];    // instance-norm (mean, rsqrt(var+eps))

// ---------------------------------------------------------------------------
// 5x5 SAME conv, 256 -> 1024, NHWC. Implicit GEMM.
// Block: 256 threads -> 64 pixels (8x8 tile) x 64 output channels.
// Thread: 4 pixels x 4 channels.
// grid = (6 spatial tiles, 16 co tiles, n_images)
// ---------------------------------------------------------------------------
template <bool ACCUM>
__global__ __launch_bounds__(256, 2) void conv5x5(
    const float* __restrict__ in, size_t in_img_stride,
    const float* __restrict__ wt,          // [5,5,256,1024]
    const float* __restrict__ bias,        // [1024] (ignored if ACCUM)
    float* __restrict__ out, size_t out_img_stride)
{
    extern __shared__ __align__(16) float sm[];
    float* s_patch = sm;                   // [KC][PSTR]
    float* s_w     = sm + KC * PSTR;       // [NTAP][KC][CO_TILE]

    const int tid = threadIdx.x;
    const int img = blockIdx.z;
    const int co0 = blockIdx.y * CO_TILE;
    const int sp  = blockIdx.x;
    const int ty0 = (sp / 3) * 8;
    const int tx0 = (sp % 3) * 8;

    const float* in_img  = in  + (size_t)img * in_img_stride;
    float*       out_img = out + (size_t)img * out_img_stride;

    const int cg  = tid & 15;              // channel group -> co = co0 + cg*4..+3
    const int pg  = tid >> 4;              // pixel group (0..15)
    const int py  = pg >> 1;               // row in 8x8 tile
    const int px0 = (pg & 1) * 4;          // col start in 8x8 tile

    float acc[4][4];
#pragma unroll
    for (int i = 0; i < 4; i++)
#pragma unroll
        for (int j = 0; j < 4; j++) acc[i][j] = 0.f;

    for (int ci0 = 0; ci0 < CIN; ci0 += KC) {
        __syncthreads();
        // ---- stage input patch: 12x12 x KC, transposed [c][pp], zero-padded
        for (int e = tid; e < KC * PP; e += 256) {
            int c  = e & (KC - 1);
            int pp = e >> 3;                    // KC == 8
            int iy = pp / PATCH, ix = pp - iy * PATCH;
            int gy = ty0 + iy - 2;
            int gx = tx0 + ix - 2;
            float v = 0.f;
            if (gy >= 0 && gy < Hh && gx >= 0 && gx < Ww)
                v = in_img[(size_t)(gy * Ww + gx) * CIN + ci0 + c];
            s_patch[c * PSTR + pp] = v;
        }
        // ---- stage weights: all 25 taps x KC x 64 (coalesced on co)
        for (int e = tid; e < NTAP * KC * CO_TILE; e += 256) {
            int co  = e & (CO_TILE - 1);
            int r   = e >> 6;
            int c   = r & (KC - 1);
            int tap = r >> 3;
            s_w[e] = wt[(size_t)(tap * CIN + ci0 + c) * COUT + co0 + co];
        }
        __syncthreads();

#pragma unroll 1
        for (int tap = 0; tap < NTAP; ++tap) {
            const int dy = tap / 5, dx = tap - dy * 5;
            const float* prow = s_patch + (py + dy) * PATCH + px0 + dx;
            const float* wrow = s_w + tap * (KC * CO_TILE) + cg * 4;
#pragma unroll
            for (int c = 0; c < KC; ++c) {
                float a0 = prow[c * PSTR + 0];
                float a1 = prow[c * PSTR + 1];
                float a2 = prow[c * PSTR + 2];
                float a3 = prow[c * PSTR + 3];
                float4 b4 = *(const float4*)(wrow + c * CO_TILE);
                acc[0][0] = fmaf(a0, b4.x, acc[0][0]);
                acc[0][1] = fmaf(a0, b4.y, acc[0][1]);
                acc[0][2] = fmaf(a0, b4.z, acc[0][2]);
                acc[0][3] = fmaf(a0, b4.w, acc[0][3]);
                acc[1][0] = fmaf(a1, b4.x, acc[1][0]);
                acc[1][1] = fmaf(a1, b4.y, acc[1][1]);
                acc[1][2] = fmaf(a1, b4.z, acc[1][2]);
                acc[1][3] = fmaf(a1, b4.w, acc[1][3]);
                acc[2][0] = fmaf(a2, b4.x, acc[2][0]);
                acc[2][1] = fmaf(a2, b4.y, acc[2][1]);
                acc[2][2] = fmaf(a2, b4.z, acc[2][2]);
                acc[2][3] = fmaf(a2, b4.w, acc[2][3]);
                acc[3][0] = fmaf(a3, b4.x, acc[3][0]);
                acc[3][1] = fmaf(a3, b4.y, acc[3][1]);
                acc[3][2] = fmaf(a3, b4.z, acc[3][2]);
                acc[3][3] = fmaf(a3, b4.w, acc[3][3]);
            }
        }
    }

    // ---- writeback: pixels (ty0+py, tx0+px0+i), channels co0+cg*4..+3
    const int oy = ty0 + py;
    float4 bv = make_float4(0.f, 0.f, 0.f, 0.f);
    if (!ACCUM) bv = *(const float4*)(bias + co0 + cg * 4);
#pragma unroll
    for (int i = 0; i < 4; i++) {
        int ox = tx0 + px0 + i;
        if (ox < Ww) {
            float4* o = (float4*)&out_img[(size_t)(oy * Ww + ox) * COUT + co0 + cg * 4];
            if (ACCUM) {
                float4 v = *o;
                v.x += acc[i][0]; v.y += acc[i][1]; v.z += acc[i][2]; v.w += acc[i][3];
                *o = v;
            } else {
                *o = make_float4(acc[i][0] + bv.x, acc[i][1] + bv.y,
                                 acc[i][2] + bv.z, acc[i][3] + bv.w);
            }
        }
    }
}

// ---------------------------------------------------------------------------
// LSTM pointwise update for one timestep
// ---------------------------------------------------------------------------
__device__ __forceinline__ float hsig(float x)
{
    return fminf(fmaxf(0.2f * x + 0.5f, 0.f), 1.f);
}

__global__ void lstm_point(const float* __restrict__ xg_t,   // + t*HW*COUT
                           float* __restrict__ cbuf,
                           float* __restrict__ h_out,        // + t*HW*Ff
                           int first)
{
    int idx = blockIdx.x * 256 + threadIdx.x;
    if (idx >= (int)STATE_ELEMS) return;
    int b   = idx / (HW * Ff);
    int rem = idx - b * (HW * Ff);
    int pix = rem >> 8;
    int ch  = rem & 255;
    const float* g = xg_t + (size_t)b * (Tt * HW * COUT) + (size_t)pix * COUT + ch;
    float i_ = hsig(g[0]);
    float f_ = hsig(g[256]);
    float cc = fmaxf(g[512], 0.f);
    float o_ = hsig(g[768]);
    float cp = first ? 0.f : cbuf[idx];
    float cn = f_ * cp + i_ * cc;
    cbuf[idx] = cn;
    h_out[(size_t)b * (Tt * HW * Ff) + rem] = o_ * fmaxf(cn, 0.f);
}

// ---------------------------------------------------------------------------
// Instance norm: per (batch, channel) over T*H*W
// ---------------------------------------------------------------------------
__global__ void inorm_stats(const float* __restrict__ seq, float2* __restrict__ stats)
{
    int b  = blockIdx.x >> 8;
    int ch = blockIdx.x & 255;
    const float* base = seq + (size_t)b * Tt * HW * Ff + ch;
    float s = 0.f, s2 = 0.f;
    for (int e = threadIdx.x; e < Tt * HW; e += 256) {
        float v = base[(size_t)e * Ff];
        s += v; s2 += v * v;
    }
    __shared__ float rs[256], rq[256];
    rs[threadIdx.x] = s;  rq[threadIdx.x] = s2;
    __syncthreads();
    for (int st = 128; st > 0; st >>= 1) {
        if (threadIdx.x < st) {
            rs[threadIdx.x] += rs[threadIdx.x + st];
            rq[threadIdx.x] += rq[threadIdx.x + st];
        }
        __syncthreads();
    }
    if (threadIdx.x == 0) {
        const float inv = 1.f / (float)(Tt * HW);
        float mu  = rs[0] * inv;
        float var = rq[0] * inv - mu * mu;
        stats[blockIdx.x] = make_float2(mu, rsqrtf(var + 1e-3f));
    }
}

__global__ void inorm_apply(const float* __restrict__ in,
                            const float2* __restrict__ stats,
                            const float* __restrict__ gamma,
                            const float* __restrict__ beta,
                            float* __restrict__ out)
{
    size_t idx = (size_t)blockIdx.x * 256 + threadIdx.x;
    if (idx >= SEQ_ELEMS) return;
    int ch = (int)(idx & 255);
    int b  = (int)(idx / ((size_t)Tt * HW * Ff));
    float2 st = stats[b * 256 + ch];
    out[idx] = gamma[ch] * (in[idx] - st.x) * st.y + beta[ch];
}

// ---------------------------------------------------------------------------
// Final-state copy (h2 = seq2[:, T-1] pre-norm, c2 = cell buffer)
// ---------------------------------------------------------------------------
__global__ void copy_states(const float* __restrict__ seq2,
                            const float* __restrict__ cbuf,
                            float* __restrict__ h2, float* __restrict__ c2)
{
    int idx = blockIdx.x * 256 + threadIdx.x;
    if (idx >= (int)STATE_ELEMS) return;
    int b   = idx / (HW * Ff);
    int rem = idx - b * (HW * Ff);
    h2[idx] = seq2[(size_t)b * Tt * HW * Ff + (size_t)(Tt - 1) * HW * Ff + rem];
    c2[idx] = cbuf[idx];
}

// ---------------------------------------------------------------------------
// Orchestration
// ---------------------------------------------------------------------------
extern "C" void kernel_launch(void* const* d_in, const int* /*in_sizes*/, int /*n_in*/,
                              void* d_out, int /*out_size*/)
{
    const float* x   = (const float*)d_in[0];
    const float* k1  = (const float*)d_in[1];
    const float* rk1 = (const float*)d_in[2];
    const float* b1  = (const float*)d_in[3];
    const float* g1  = (const float*)d_in[4];
    const float* bt1 = (const float*)d_in[5];
    const float* k2  = (const float*)d_in[6];
    const float* rk2 = (const float*)d_in[7];
    const float* b2  = (const float*)d_in[8];
    const float* g2  = (const float*)d_in[9];
    const float* bt2 = (const float*)d_in[10];

    float* out    = (float*)d_out;
    float* out_h2 = out + SEQ_ELEMS;
    float* out_c2 = out_h2 + STATE_ELEMS;

    float *xg, *seq1, *seq2, *cbuf;
    float2* stats;
    cudaGetSymbolAddress((void**)&xg,    g_xg);
    cudaGetSymbolAddress((void**)&seq1,  g_seq1);
    cudaGetSymbolAddress((void**)&seq2,  g_seq2);
    cudaGetSymbolAddress((void**)&cbuf,  g_c);
    cudaGetSymbolAddress((void**)&stats, g_stats);

    cudaFuncSetAttribute(conv5x5<false>, cudaFuncAttributeMaxDynamicSharedMemorySize, SMEM_BYTES);
    cudaFuncSetAttribute(conv5x5<true>,  cudaFuncAttributeMaxDynamicSharedMemorySize, SMEM_BYTES);

    const dim3 cgrid(6, 16, Bb * Tt);   // batched input conv (64 images)
    const dim3 rgrid(6, 16, Bb);        // recurrent conv (4 images)
    const int  pblocks = (int)((STATE_ELEMS + 255) / 256);
    const int  ablocks = (int)((SEQ_ELEMS + 255) / 256);

    // ---------------- Layer 1 ----------------
    conv5x5<false><<<cgrid, 256, SMEM_BYTES>>>(
        x, (size_t)HW * CIN, k1, b1, xg, (size_t)HW * COUT);

    for (int t = 0; t < Tt; ++t) {
        if (t > 0)
            conv5x5<true><<<rgrid, 256, SMEM_BYTES>>>(
                seq1 + (size_t)(t - 1) * HW * Ff, (size_t)Tt * HW * Ff,
                rk1, nullptr,
                xg + (size_t)t * HW * COUT, (size_t)Tt * HW * COUT);
        lstm_point<<<pblocks, 256>>>(xg + (size_t)t * HW * COUT, cbuf,
                                     seq1 + (size_t)t * HW * Ff, t == 0);
    }
    inorm_stats<<<Bb * Ff, 256>>>(seq1, stats);
    inorm_apply<<<ablocks, 256>>>(seq1, stats, g1, bt1, seq1);

    // ---------------- Layer 2 ----------------
    conv5x5<false><<<cgrid, 256, SMEM_BYTES>>>(
        seq1, (size_t)HW * Ff, k2, b2, xg, (size_t)HW * COUT);

    for (int t = 0; t < Tt; ++t) {
        if (t > 0)
            conv5x5<true><<<rgrid, 256, SMEM_BYTES>>>(
                seq2 + (size_t)(t - 1) * HW * Ff, (size_t)Tt * HW * Ff,
                rk2, nullptr,
                xg + (size_t)t * HW * COUT, (size_t)Tt * HW * COUT);
        lstm_point<<<pblocks, 256>>>(xg + (size_t)t * HW * COUT, cbuf,
                                     seq2 + (size_t)t * HW * Ff, t == 0);
    }

    copy_states<<<pblocks, 256>>>(seq2, cbuf, out_h2, out_c2);
    inorm_stats<<<Bb * Ff, 256>>>(seq2, stats);
    inorm_apply<<<ablocks, 256>>>(seq2, stats, g2, bt2, out);
}

// round 3
// speedup vs baseline: 2.2864x; 2.2864x over previous
#include <cuda_runtime.h>
#include <cuda_bf16.h>
#include <cstdint>
#include <math.h>

// ---------------------------------------------------------------------------
// Problem constants
// ---------------------------------------------------------------------------
namespace {
constexpr int Hh   = 16;
constexpr int Ww   = 21;
constexpr int HW   = Hh * Ww;        // 336
constexpr int CIN  = 256;
constexpr int COUT = 1024;           // 4*F
constexpr int Tt   = 16;
constexpr int Bb   = 4;
constexpr int Ff   = 256;
constexpr int KTOT = 25 * CIN;       // 6400

constexpr size_t SEQ_ELEMS   = (size_t)Bb * Tt * HW * Ff;      // 5,505,024
constexpr size_t STATE_ELEMS = (size_t)Bb * HW * Ff;           // 344,064
constexpr size_t XG_ELEMS    = (size_t)Bb * Tt * HW * COUT;    // 22,020,096
constexpr size_t W_ELEMS     = (size_t)KTOT * COUT;            // 6,553,600

// conv tiling
constexpr int KCH    = 64;                   // k per chunk
constexpr int NCHUNK = KTOT / KCH;           // 100
constexpr int MT     = 128;                  // CTA pixels
constexpr int NT     = 64;                   // CTA cout
constexpr int SROW_B = 144;                  // padded row stride bytes (72 bf16)

constexpr int A_T_B   = MT * SROW_B;         // 18432 B (one A tile)
constexpr int B_T_B   = NT * SROW_B;         // 9216 B
constexpr int AHI_OFF = 0;
constexpr int ALO_OFF = A_T_B;               // 18432
constexpr int BHI_OFF = 2 * A_T_B;           // 36864
constexpr int BLO_OFF = 2 * A_T_B + B_T_B;   // 46080
constexpr int SMEM_TOT = 2 * A_T_B + 2 * B_T_B;  // 55296 B
}

// ---------------------------------------------------------------------------
// Scratch (device globals — no allocation allowed)
// ---------------------------------------------------------------------------
__device__ float  g_xg[XG_ELEMS];                 // gate pre-activations
__device__ float  g_seq1[SEQ_ELEMS];
__device__ float  g_seq2[SEQ_ELEMS];
__device__ float  g_c[STATE_ELEMS];
__device__ float2 g_stats[Bb * Ff];

__device__ __align__(16) __nv_bfloat16 g_ahi[SEQ_ELEMS];  // conv input split
__device__ __align__(16) __nv_bfloat16 g_alo[SEQ_ELEMS];
__device__ __align__(16) __nv_bfloat16 g_hhi[SEQ_ELEMS];  // hidden-state split
__device__ __align__(16) __nv_bfloat16 g_hlo[SEQ_ELEMS];
__device__ __align__(16) __nv_bfloat16 g_whi[4][W_ELEMS]; // transposed weights [co][k]
__device__ __align__(16) __nv_bfloat16 g_wlo[4][W_ELEMS];

// ---------------------------------------------------------------------------
// mma.sync m16n8k16 bf16 (portable PTX, maps to HMMA on sm_103)
// ---------------------------------------------------------------------------
__device__ __forceinline__ void mma16816(float* d, const uint32_t* a, const uint32_t* b)
{
    asm volatile(
        "mma.sync.aligned.m16n8k16.row.col.f32.bf16.bf16.f32 "
        "{%0,%1,%2,%3}, {%4,%5,%6,%7}, {%8,%9}, {%0,%1,%2,%3};"
        : "+f"(d[0]), "+f"(d[1]), "+f"(d[2]), "+f"(d[3])
        : "r"(a[0]), "r"(a[1]), "r"(a[2]), "r"(a[3]), "r"(b[0]), "r"(b[1]));
}

// ---------------------------------------------------------------------------
// Implicit-GEMM 5x5 SAME conv, 256 -> 1024, bf16 3-term split on tensor cores.
// grid = (ceil(Mtot/128), 16), block = 256 (8 warps: 2m x 4n, warp tile 64x16)
// ---------------------------------------------------------------------------
template <bool ACCUM>
__global__ __launch_bounds__(256, 2) void conv_mma(
    const __nv_bfloat16* __restrict__ a_hi, const __nv_bfloat16* __restrict__ a_lo,
    size_t a_img_stride,
    const __nv_bfloat16* __restrict__ w_hi, const __nv_bfloat16* __restrict__ w_lo,
    const float* __restrict__ bias,
    float* __restrict__ out, size_t out_img_stride, int Mtot)
{
    extern __shared__ __align__(16) char sm[];

    const int tid  = threadIdx.x;
    const int wid  = tid >> 5;
    const int lane = tid & 31;
    const int m0   = blockIdx.x * MT;
    const int co0  = blockIdx.y * NT;

    // ---- staging geometry
    const int arow  = tid >> 1;          // 0..127 (A tile row / pixel)
    const int ahalf = tid & 1;           // half of the 64-k row
    int pc = m0 + arow; if (pc >= Mtot) pc = Mtot - 1;
    const int img = pc / HW;
    const int rm  = pc - img * HW;
    const int py  = rm / Ww;
    const int px  = rm - py * Ww;
    const __nv_bfloat16* aimg_hi = a_hi + (size_t)img * a_img_stride;
    const __nv_bfloat16* aimg_lo = a_lo + (size_t)img * a_img_stride;

    const int brow = tid >> 2;           // 0..63 (B tile row = cout)
    const int bq   = tid & 3;            // quarter of the 64-k row
    const __nv_bfloat16* wrow_hi = w_hi + (size_t)(co0 + brow) * KTOT;
    const __nv_bfloat16* wrow_lo = w_lo + (size_t)(co0 + brow) * KTOT;

    // ---- compute geometry
    const int wm  = wid & 1;             // 0..1
    const int wn  = wid >> 1;            // 0..3
    const int m0w = wm * 64;
    const int n0w = wn * 16;
    const int g   = lane >> 2;           // 0..7
    const int tk  = (lane & 3) * 2;      // 0,2,4,6

    float acc[4][2][4];
#pragma unroll
    for (int mf = 0; mf < 4; mf++)
#pragma unroll
        for (int nf = 0; nf < 2; nf++)
#pragma unroll
            for (int r = 0; r < 4; r++) acc[mf][nf][r] = 0.f;

    for (int c = 0; c < NCHUNK; ++c) {
        // ---------- stage chunk c ----------
        {
            const int tp  = c >> 2;
            const int ci0 = (c & 3) << 6;
            const int dy  = tp / 5;
            const int dx  = tp - dy * 5;
            const int gy  = py + dy - 2;
            const int gx  = px + dx - 2;

            uint4 vh[4], vl[4];
            if (gy >= 0 && gy < Hh && gx >= 0 && gx < Ww) {
                const size_t off = (((size_t)(gy * Ww + gx)) << 8) + ci0 + (ahalf << 5);
                const uint4* sh = (const uint4*)(aimg_hi + off);
                const uint4* sl = (const uint4*)(aimg_lo + off);
#pragma unroll
                for (int q = 0; q < 4; q++) { vh[q] = sh[q]; vl[q] = sl[q]; }
            } else {
                const uint4 z = make_uint4(0, 0, 0, 0);
#pragma unroll
                for (int q = 0; q < 4; q++) { vh[q] = z; vl[q] = z; }
            }
            const uint4* bh = (const uint4*)(wrow_hi + (c << 6) + (bq << 4));
            const uint4* bl = (const uint4*)(wrow_lo + (c << 6) + (bq << 4));
            const uint4 wh0 = bh[0], wh1 = bh[1];
            const uint4 wl0 = bl[0], wl1 = bl[1];

            char* pa = sm + arow * SROW_B + (ahalf << 6);
#pragma unroll
            for (int q = 0; q < 4; q++) {
                *(uint4*)(pa + AHI_OFF + q * 16) = vh[q];
                *(uint4*)(pa + ALO_OFF + q * 16) = vl[q];
            }
            char* pb = sm + brow * SROW_B + (bq << 5);
            *(uint4*)(pb + BHI_OFF)      = wh0;
            *(uint4*)(pb + BHI_OFF + 16) = wh1;
            *(uint4*)(pb + BLO_OFF)      = wl0;
            *(uint4*)(pb + BLO_OFF + 16) = wl1;
        }
        __syncthreads();

        // ---------- compute chunk c ----------
#pragma unroll
        for (int ks = 0; ks < 4; ++ks) {
            const int kb = (ks * 16 + tk) * 2;   // byte offset within row

            uint32_t ah[4][4], al[4][4];
#pragma unroll
            for (int mf = 0; mf < 4; mf++) {
                const char* pa = sm + (m0w + mf * 16 + g) * SROW_B + kb;
                ah[mf][0] = *(const uint32_t*)(pa + AHI_OFF);
                ah[mf][1] = *(const uint32_t*)(pa + AHI_OFF + 8 * SROW_B);
                ah[mf][2] = *(const uint32_t*)(pa + AHI_OFF + 16);
                ah[mf][3] = *(const uint32_t*)(pa + AHI_OFF + 8 * SROW_B + 16);
                al[mf][0] = *(const uint32_t*)(pa + ALO_OFF);
                al[mf][1] = *(const uint32_t*)(pa + ALO_OFF + 8 * SROW_B);
                al[mf][2] = *(const uint32_t*)(pa + ALO_OFF + 16);
                al[mf][3] = *(const uint32_t*)(pa + ALO_OFF + 8 * SROW_B + 16);
            }
            uint32_t bh[2][2], bl[2][2];
#pragma unroll
            for (int nf = 0; nf < 2; nf++) {
                const char* pb = sm + (n0w + nf * 8 + g) * SROW_B + kb;
                bh[nf][0] = *(const uint32_t*)(pb + BHI_OFF);
                bh[nf][1] = *(const uint32_t*)(pb + BHI_OFF + 16);
                bl[nf][0] = *(const uint32_t*)(pb + BLO_OFF);
                bl[nf][1] = *(const uint32_t*)(pb + BLO_OFF + 16);
            }
#pragma unroll
            for (int mf = 0; mf < 4; mf++)
#pragma unroll
                for (int nf = 0; nf < 2; nf++) {
                    mma16816(acc[mf][nf], ah[mf], bh[nf]);   // hi*hi
                    mma16816(acc[mf][nf], ah[mf], bl[nf]);   // hi*lo
                    mma16816(acc[mf][nf], al[mf], bh[nf]);   // lo*hi
                }
        }
        __syncthreads();
    }

    // ---------- epilogue ----------
#pragma unroll
    for (int mf = 0; mf < 4; mf++) {
#pragma unroll
        for (int half = 0; half < 2; half++) {
            const int p = m0 + m0w + mf * 16 + g + half * 8;
            if (p >= Mtot) continue;
            const int im = p / HW;
            const int pp = p - im * HW;
            float* orow = out + (size_t)im * out_img_stride + (size_t)pp * COUT + co0;
#pragma unroll
            for (int nf = 0; nf < 2; nf++) {
                const int col = n0w + nf * 8 + tk;
                float v0 = acc[mf][nf][half * 2 + 0];
                float v1 = acc[mf][nf][half * 2 + 1];
                float2* dst = (float2*)(orow + col);
                if (ACCUM) {
                    float2 o = *dst;
                    dst->x = o.x + v0;
                    dst->y = o.y + v1;
                } else {
                    dst->x = v0 + bias[co0 + col];
                    dst->y = v1 + bias[co0 + col + 1];
                }
            }
        }
    }
}

// ---------------------------------------------------------------------------
// Weight transpose + bf16 split: w[k][co] (f32) -> whi/wlo[co][k] (bf16)
// ---------------------------------------------------------------------------
__global__ void wsplit(const float* __restrict__ w,
                       __nv_bfloat16* __restrict__ whi, __nv_bfloat16* __restrict__ wlo)
{
    __shared__ float tile[32][33];
    const int k0  = blockIdx.x * 32;
    const int co0 = blockIdx.y * 32;
    const int tx = threadIdx.x, ty = threadIdx.y;
#pragma unroll
    for (int i = 0; i < 4; i++)
        tile[ty + i * 8][tx] = w[(size_t)(k0 + ty + i * 8) * COUT + co0 + tx];
    __syncthreads();
#pragma unroll
    for (int i = 0; i < 4; i++) {
        const int co = co0 + ty + i * 8;
        const int k  = k0 + tx;
        const float v = tile[tx][ty + i * 8];
        const __nv_bfloat16 h = __float2bfloat16(v);
        whi[(size_t)co * KTOT + k] = h;
        wlo[(size_t)co * KTOT + k] = __float2bfloat16(v - __bfloat162float(h));
    }
}

// ---------------------------------------------------------------------------
// f32 -> bf16 hi/lo split (elementwise)
// ---------------------------------------------------------------------------
__global__ void xsplit(const float* __restrict__ in,
                       __nv_bfloat16* __restrict__ hi, __nv_bfloat16* __restrict__ lo,
                       size_t n)
{
    size_t i = (size_t)blockIdx.x * 256 + threadIdx.x;
    if (i >= n) return;
    const float v = in[i];
    const __nv_bfloat16 h = __float2bfloat16(v);
    hi[i] = h;
    lo[i] = __float2bfloat16(v - __bfloat162float(h));
}

// ---------------------------------------------------------------------------
// LSTM pointwise (+ emit hidden-state bf16 split)
// ---------------------------------------------------------------------------
__device__ __forceinline__ float hsig(float x)
{
    return fminf(fmaxf(0.2f * x + 0.5f, 0.f), 1.f);
}

__global__ void lstm_point(const float* __restrict__ xg_t,
                           float* __restrict__ cbuf,
                           float* __restrict__ h_out,
                           __nv_bfloat16* __restrict__ hhi,
                           __nv_bfloat16* __restrict__ hlo,
                           int first)
{
    int idx = blockIdx.x * 256 + threadIdx.x;
    if (idx >= (int)STATE_ELEMS) return;
    int b   = idx / (HW * Ff);
    int rem = idx - b * (HW * Ff);
    int pix = rem >> 8;
    int ch  = rem & 255;
    const float* gp = xg_t + (size_t)b * (Tt * HW * COUT) + (size_t)pix * COUT + ch;
    float i_ = hsig(gp[0]);
    float f_ = hsig(gp[256]);
    float cc = fmaxf(gp[512], 0.f);
    float o_ = hsig(gp[768]);
    float cp = first ? 0.f : cbuf[idx];
    float cn = f_ * cp + i_ * cc;
    cbuf[idx] = cn;
    float h = o_ * fmaxf(cn, 0.f);
    size_t oidx = (size_t)b * (Tt * HW * Ff) + rem;
    h_out[oidx] = h;
    __nv_bfloat16 hb = __float2bfloat16(h);
    hhi[oidx] = hb;
    hlo[oidx] = __float2bfloat16(h - __bfloat162float(hb));
}

// ---------------------------------------------------------------------------
// Instance norm
// ---------------------------------------------------------------------------
__global__ void inorm_stats(const float* __restrict__ seq, float2* __restrict__ stats)
{
    int b  = blockIdx.x >> 8;
    int ch = blockIdx.x & 255;
    const float* base = seq + (size_t)b * Tt * HW * Ff + ch;
    float s = 0.f, s2 = 0.f;
    for (int e = threadIdx.x; e < Tt * HW; e += 256) {
        float v = base[(size_t)e * Ff];
        s += v; s2 += v * v;
    }
    __shared__ float rs[256], rq[256];
    rs[threadIdx.x] = s;  rq[threadIdx.x] = s2;
    __syncthreads();
    for (int st = 128; st > 0; st >>= 1) {
        if (threadIdx.x < st) {
            rs[threadIdx.x] += rs[threadIdx.x + st];
            rq[threadIdx.x] += rq[threadIdx.x + st];
        }
        __syncthreads();
    }
    if (threadIdx.x == 0) {
        const float inv = 1.f / (float)(Tt * HW);
        float mu  = rs[0] * inv;
        float var = rq[0] * inv - mu * mu;
        stats[blockIdx.x] = make_float2(mu, rsqrtf(var + 1e-3f));
    }
}

__global__ void inorm_apply(const float* __restrict__ in,
                            const float2* __restrict__ stats,
                            const float* __restrict__ gamma,
                            const float* __restrict__ beta,
                            float* __restrict__ out,
                            __nv_bfloat16* __restrict__ shi,
                            __nv_bfloat16* __restrict__ slo)
{
    size_t idx = (size_t)blockIdx.x * 256 + threadIdx.x;
    if (idx >= SEQ_ELEMS) return;
    int ch = (int)(idx & 255);
    int b  = (int)(idx / ((size_t)Tt * HW * Ff));
    float2 st = stats[b * 256 + ch];
    float v = gamma[ch] * (in[idx] - st.x) * st.y + beta[ch];
    out[idx] = v;
    if (shi) {
        __nv_bfloat16 h = __float2bfloat16(v);
        shi[idx] = h;
        slo[idx] = __float2bfloat16(v - __bfloat162float(h));
    }
}

__global__ void copy_states(const float* __restrict__ seq2,
                            const float* __restrict__ cbuf,
                            float* __restrict__ h2, float* __restrict__ c2)
{
    int idx = blockIdx.x * 256 + threadIdx.x;
    if (idx >= (int)STATE_ELEMS) return;
    int b   = idx / (HW * Ff);
    int rem = idx - b * (HW * Ff);
    h2[idx] = seq2[(size_t)b * Tt * HW * Ff + (size_t)(Tt - 1) * HW * Ff + rem];
    c2[idx] = cbuf[idx];
}

// ---------------------------------------------------------------------------
// Orchestration
// ---------------------------------------------------------------------------
extern "C" void kernel_launch(void* const* d_in, const int* /*in_sizes*/, int /*n_in*/,
                              void* d_out, int /*out_size*/)
{
    const float* x   = (const float*)d_in[0];
    const float* k1  = (const float*)d_in[1];
    const float* rk1 = (const float*)d_in[2];
    const float* b1  = (const float*)d_in[3];
    const float* g1  = (const float*)d_in[4];
    const float* bt1 = (const float*)d_in[5];
    const float* k2  = (const float*)d_in[6];
    const float* rk2 = (const float*)d_in[7];
    const float* b2  = (const float*)d_in[8];
    const float* g2  = (const float*)d_in[9];
    const float* bt2 = (const float*)d_in[10];

    float* out    = (float*)d_out;
    float* out_h2 = out + SEQ_ELEMS;
    float* out_c2 = out_h2 + STATE_ELEMS;

    float *xg, *seq1, *seq2, *cbuf;
    float2* stats;
    __nv_bfloat16 *ahi, *alo, *hhi, *hlo, *whi, *wlo;
    cudaGetSymbolAddress((void**)&xg,    g_xg);
    cudaGetSymbolAddress((void**)&seq1,  g_seq1);
    cudaGetSymbolAddress((void**)&seq2,  g_seq2);
    cudaGetSymbolAddress((void**)&cbuf,  g_c);
    cudaGetSymbolAddress((void**)&stats, g_stats);
    cudaGetSymbolAddress((void**)&ahi,   g_ahi);
    cudaGetSymbolAddress((void**)&alo,   g_alo);
    cudaGetSymbolAddress((void**)&hhi,   g_hhi);
    cudaGetSymbolAddress((void**)&hlo,   g_hlo);
    cudaGetSymbolAddress((void**)&whi,   g_whi);
    cudaGetSymbolAddress((void**)&wlo,   g_wlo);

    cudaFuncSetAttribute(conv_mma<false>, cudaFuncAttributeMaxDynamicSharedMemorySize, SMEM_TOT);
    cudaFuncSetAttribute(conv_mma<true>,  cudaFuncAttributeMaxDynamicSharedMemorySize, SMEM_TOT);

    const dim3 wgrid(KTOT / 32, COUT / 32);
    const dim3 wblk(32, 8);
    wsplit<<<wgrid, wblk>>>(k1,  whi + 0 * W_ELEMS, wlo + 0 * W_ELEMS);
    wsplit<<<wgrid, wblk>>>(rk1, whi + 1 * W_ELEMS, wlo + 1 * W_ELEMS);
    wsplit<<<wgrid, wblk>>>(k2,  whi + 2 * W_ELEMS, wlo + 2 * W_ELEMS);
    wsplit<<<wgrid, wblk>>>(rk2, whi + 3 * W_ELEMS, wlo + 3 * W_ELEMS);

    const int sblocks = (int)((SEQ_ELEMS + 255) / 256);
    xsplit<<<sblocks, 256>>>(x, ahi, alo, SEQ_ELEMS);

    const int Min  = Bb * Tt * HW;                   // 21504
    const int Mrec = Bb * HW;                        // 1344
    const dim3 igrid(Min / MT, COUT / NT);           // (168, 16)
    const dim3 rgrid((Mrec + MT - 1) / MT, COUT / NT); // (11, 16)
    const int pblocks = (int)((STATE_ELEMS + 255) / 256);

    // ---------------- Layer 1 ----------------
    conv_mma<false><<<igrid, 256, SMEM_TOT>>>(
        ahi, alo, (size_t)HW * CIN, whi + 0 * W_ELEMS, wlo + 0 * W_ELEMS,
        b1, xg, (size_t)HW * COUT, Min);

    for (int t = 0; t < Tt; ++t) {
        if (t > 0)
            conv_mma<true><<<rgrid, 256, SMEM_TOT>>>(
                hhi + (size_t)(t - 1) * HW * Ff, hlo + (size_t)(t - 1) * HW * Ff,
                (size_t)Tt * HW * Ff,
                whi + 1 * W_ELEMS, wlo + 1 * W_ELEMS, nullptr,
                xg + (size_t)t * HW * COUT, (size_t)Tt * HW * COUT, Mrec);
        lstm_point<<<pblocks, 256>>>(xg + (size_t)t * HW * COUT, cbuf,
                                     seq1 + (size_t)t * HW * Ff,
                                     hhi + (size_t)t * HW * Ff,
                                     hlo + (size_t)t * HW * Ff, t == 0);
    }
    inorm_stats<<<Bb * Ff, 256>>>(seq1, stats);
    inorm_apply<<<sblocks, 256>>>(seq1, stats, g1, bt1, seq1, ahi, alo);

    // ---------------- Layer 2 ----------------
    conv_mma<false><<<igrid, 256, SMEM_TOT>>>(
        ahi, alo, (size_t)HW * CIN, whi + 2 * W_ELEMS, wlo + 2 * W_ELEMS,
        b2, xg, (size_t)HW * COUT, Min);

    for (int t = 0; t < Tt; ++t) {
        if (t > 0)
            conv_mma<true><<<rgrid, 256, SMEM_TOT>>>(
                hhi + (size_t)(t - 1) * HW * Ff, hlo + (size_t)(t - 1) * HW * Ff,
                (size_t)Tt * HW * Ff,
                whi + 3 * W_ELEMS, wlo + 3 * W_ELEMS, nullptr,
                xg + (size_t)t * HW * COUT, (size_t)Tt * HW * COUT, Mrec);
        lstm_point<<<pblocks, 256>>>(xg + (size_t)t * HW * COUT, cbuf,
                                     seq2 + (size_t)t * HW * Ff,
                                     hhi + (size_t)t * HW * Ff,
                                     hlo + (size_t)t * HW * Ff, t == 0);
    }

    copy_states<<<pblocks, 256>>>(seq2, cbuf, out_h2, out_c2);
    inorm_stats<<<Bb * Ff, 256>>>(seq2, stats);
    inorm_apply<<<sblocks, 256>>>(seq2, stats, g2, bt2, out, nullptr, nullptr);
}

// round 4
// speedup vs baseline: 2.9697x; 1.2988x over previous
#include <cuda_runtime.h>
#include <cuda_bf16.h>
#include <cstdint>
#include <math.h>

// ---------------------------------------------------------------------------
// Problem constants
// ---------------------------------------------------------------------------
namespace {
constexpr int Hh   = 16;
constexpr int Ww   = 21;
constexpr int HW   = Hh * Ww;        // 336
constexpr int CIN  = 256;
constexpr int COUT = 1024;           // 4*F
constexpr int Tt   = 16;
constexpr int Bb   = 4;
constexpr int Ff   = 256;
constexpr int KTOT = 25 * CIN;       // 6400

constexpr size_t SEQ_ELEMS   = (size_t)Bb * Tt * HW * Ff;      // 5,505,024
constexpr size_t STATE_ELEMS = (size_t)Bb * HW * Ff;           // 344,064
constexpr size_t XG_ELEMS    = (size_t)Bb * Tt * HW * COUT;    // 22,020,096
constexpr size_t XG2_ELEMS   = (size_t)Bb * HW * COUT;         // 1,376,256
constexpr size_t W_ELEMS     = (size_t)KTOT * COUT;            // 6,553,600

// conv tiling
constexpr int NCHUNK = KTOT / 64;            // 100 chunks of k=64
constexpr int MT     = 128;                  // CTA pixels
constexpr int NT     = 64;                   // CTA cout
constexpr int SROW_B = 144;                  // padded row stride (bytes)

constexpr int A_T_B   = MT * SROW_B;         // 18432
constexpr int B_T_B   = NT * SROW_B;         // 9216
constexpr int AHI_OFF = 0;
constexpr int ALO_OFF = A_T_B;               // 18432
constexpr int BHI_OFF = 2 * A_T_B;           // 36864
constexpr int BLO_OFF = 2 * A_T_B + B_T_B;   // 46080
constexpr int BUF_B   = 2 * A_T_B + 2 * B_T_B;   // 55296 per stage
constexpr int SMEM_TOT = 2 * BUF_B;              // 110592 (double buffer)
}

// ---------------------------------------------------------------------------
// Scratch (device globals — no allocation allowed)
// ---------------------------------------------------------------------------
__device__ float  g_xg[XG_ELEMS];                 // gate pre-activations
__device__ float  g_xg2[XG2_ELEMS];               // split-K partial (one timestep)
__device__ float  g_seq1[SEQ_ELEMS];
__device__ float  g_seq2[SEQ_ELEMS];
__device__ float  g_c[STATE_ELEMS];
__device__ float2 g_stats[Bb * Ff];

__device__ __align__(16) __nv_bfloat16 g_ahi[SEQ_ELEMS];
__device__ __align__(16) __nv_bfloat16 g_alo[SEQ_ELEMS];
__device__ __align__(16) __nv_bfloat16 g_hhi[SEQ_ELEMS];
__device__ __align__(16) __nv_bfloat16 g_hlo[SEQ_ELEMS];
__device__ __align__(16) __nv_bfloat16 g_whi[4][W_ELEMS]; // [co][k]
__device__ __align__(16) __nv_bfloat16 g_wlo[4][W_ELEMS];

// ---------------------------------------------------------------------------
// PTX helpers (all portable to plain sm_103)
// ---------------------------------------------------------------------------
__device__ __forceinline__ uint32_t smem_u32(const void* p) {
    uint32_t a;
    asm("{ .reg .u64 t; cvta.to.shared.u64 t, %1; cvt.u32.u64 %0, t; }" : "=r"(a) : "l"(p));
    return a;
}
__device__ __forceinline__ void cp16(uint32_t dst, const void* src, uint32_t srcsz) {
    asm volatile("cp.async.cg.shared.global [%0], [%1], 16, %2;"
                 :: "r"(dst), "l"(src), "r"(srcsz) : "memory");
}
#define CP_COMMIT() asm volatile("cp.async.commit_group;" ::: "memory")
#define CP_WAIT1()  asm volatile("cp.async.wait_group 1;" ::: "memory")
#define CP_WAIT0()  asm volatile("cp.async.wait_group 0;" ::: "memory")

__device__ __forceinline__ void ldsm4(uint32_t* r, uint32_t addr) {
    asm volatile("ldmatrix.sync.aligned.m8n8.x4.shared.b16 {%0,%1,%2,%3}, [%4];"
                 : "=r"(r[0]), "=r"(r[1]), "=r"(r[2]), "=r"(r[3]) : "r"(addr));
}
__device__ __forceinline__ void ldsm2(uint32_t* r, uint32_t addr) {
    asm volatile("ldmatrix.sync.aligned.m8n8.x2.shared.b16 {%0,%1}, [%2];"
                 : "=r"(r[0]), "=r"(r[1]) : "r"(addr));
}
__device__ __forceinline__ void mma16816(float* d, const uint32_t* a, const uint32_t* b)
{
    asm volatile(
        "mma.sync.aligned.m16n8k16.row.col.f32.bf16.bf16.f32 "
        "{%0,%1,%2,%3}, {%4,%5,%6,%7}, {%8,%9}, {%0,%1,%2,%3};"
        : "+f"(d[0]), "+f"(d[1]), "+f"(d[2]), "+f"(d[3])
        : "r"(a[0]), "r"(a[1]), "r"(a[2]), "r"(a[3]), "r"(b[0]), "r"(b[1]));
}

// ---------------------------------------------------------------------------
// Implicit-GEMM 5x5 SAME conv, 256 -> 1024, bf16 3-term split on tensor cores.
// cp.async double-buffered staging + ldmatrix fragment loads.
// grid = (ceil(Mtot/128), 16, Z). Z==1: full K, bias add (input conv).
// Z==2: split-K — z0 accumulates chunks [0,50) into out; z1 writes chunks
//       [50,100) to out2 (partial, no bias).
// ---------------------------------------------------------------------------
__global__ __launch_bounds__(256, 2) void conv_mma(
    const __nv_bfloat16* __restrict__ a_hi, const __nv_bfloat16* __restrict__ a_lo,
    size_t a_img_stride,
    const __nv_bfloat16* __restrict__ w_hi, const __nv_bfloat16* __restrict__ w_lo,
    const float* __restrict__ bias,
    float* __restrict__ out, size_t out_img_stride,
    float* __restrict__ out2, size_t out2_img_stride,
    int Mtot)
{
    extern __shared__ __align__(16) char sm[];
    const uint32_t smb = smem_u32(sm);

    const int tid  = threadIdx.x;
    const int lane = tid & 31;
    const int wid  = tid >> 5;
    const int m0   = blockIdx.x * MT;
    const int co0  = blockIdx.y * NT;

    // ---- K range / destination selection
    int cbeg = 0, cend = NCHUNK;
    float* dst = out;
    size_t dstride = out_img_stride;
    bool accum = false;
    const float* bs = bias;
    if (gridDim.z == 2) {
        bs = nullptr;
        if (blockIdx.z == 0) { cend = NCHUNK / 2; accum = true; }
        else { cbeg = NCHUNK / 2; dst = out2; dstride = out2_img_stride; }
    }

    // ---- staging geometry
    const int arow  = tid >> 1;
    const int ahalf = tid & 1;
    int pc = m0 + arow; if (pc >= Mtot) pc = Mtot - 1;
    const int img = pc / HW;
    const int rm  = pc - img * HW;
    const int py  = rm / Ww;
    const int px  = rm - py * Ww;
    const __nv_bfloat16* aimg_hi = a_hi + (size_t)img * a_img_stride;
    const __nv_bfloat16* aimg_lo = a_lo + (size_t)img * a_img_stride;

    const int brow = tid >> 2;
    const int bq   = tid & 3;
    const __nv_bfloat16* wrow_hi = w_hi + (size_t)(co0 + brow) * KTOT;
    const __nv_bfloat16* wrow_lo = w_lo + (size_t)(co0 + brow) * KTOT;

    const uint32_t da0 = smb + arow * SROW_B + (ahalf << 6);
    const uint32_t db0 = smb + BHI_OFF + brow * SROW_B + (bq << 5);

    auto stage = [&](int c, int buf) {
        const uint32_t bo = (uint32_t)buf * BUF_B;
        const int tp  = c >> 2;
        const int ci0 = (c & 3) << 6;
        const int dy  = tp / 5;
        const int dx  = tp - dy * 5;
        const int gy  = py + dy - 2;
        const int gx  = px + dx - 2;
        const bool inb = (gy >= 0 && gy < Hh && gx >= 0 && gx < Ww);
        const uint32_t sz = inb ? 16u : 0u;
        const size_t off = inb ? ((((size_t)(gy * Ww + gx)) << 8) + ci0 + (ahalf << 5)) : 0;
        const char* sh = (const char*)(aimg_hi + off);
        const char* sl = (const char*)(aimg_lo + off);
        const uint32_t da = da0 + bo;
#pragma unroll
        for (int q = 0; q < 4; q++) {
            cp16(da + q * 16,           sh + q * 16, sz);
            cp16(da + ALO_OFF + q * 16, sl + q * 16, sz);
        }
        const char* wh = (const char*)(wrow_hi + (c << 6) + (bq << 4));
        const char* wl = (const char*)(wrow_lo + (c << 6) + (bq << 4));
        const uint32_t db = db0 + bo;
        cp16(db,      wh,      16);
        cp16(db + 16, wh + 16, 16);
        cp16(db + (BLO_OFF - BHI_OFF),      wl,      16);
        cp16(db + (BLO_OFF - BHI_OFF) + 16, wl + 16, 16);
    };

    // ---- compute geometry
    const int wm  = wid & 1;
    const int wn  = wid >> 1;
    const int m0w = wm * 64;
    const int n0w = wn * 16;
    const int g   = lane >> 2;
    const int tk  = (lane & 3) * 2;

    // ldmatrix base addresses (buffer 0)
    uint32_t abase[4], bbase[2];
#pragma unroll
    for (int mf = 0; mf < 4; mf++)
        abase[mf] = smb + (m0w + mf * 16 + (lane & 15)) * SROW_B + ((lane & 16) ? 16 : 0);
#pragma unroll
    for (int nf = 0; nf < 2; nf++)
        bbase[nf] = smb + BHI_OFF + (n0w + nf * 8 + (lane & 7)) * SROW_B + ((lane & 8) ? 16 : 0);

    float acc[4][2][4];
#pragma unroll
    for (int mf = 0; mf < 4; mf++)
#pragma unroll
        for (int nf = 0; nf < 2; nf++)
#pragma unroll
            for (int r = 0; r < 4; r++) acc[mf][nf][r] = 0.f;

    // ---- pipeline
    stage(cbeg, 0);
    CP_COMMIT();

    for (int c = cbeg; c < cend; ++c) {
        const int buf = (c - cbeg) & 1;
        if (c + 1 < cend) {
            stage(c + 1, buf ^ 1);
            CP_COMMIT();
            CP_WAIT1();
        } else {
            CP_WAIT0();
        }
        __syncthreads();

        const uint32_t bo = (uint32_t)buf * BUF_B;
#pragma unroll
        for (int ks = 0; ks < 4; ++ks) {
            uint32_t ah[4][4], al[4][4], bh[2][2], bl[2][2];
#pragma unroll
            for (int mf = 0; mf < 4; mf++) {
                ldsm4(ah[mf], abase[mf] + bo + ks * 32);
                ldsm4(al[mf], abase[mf] + bo + ALO_OFF + ks * 32);
            }
#pragma unroll
            for (int nf = 0; nf < 2; nf++) {
                ldsm2(bh[nf], bbase[nf] + bo + ks * 32);
                ldsm2(bl[nf], bbase[nf] + bo + (BLO_OFF - BHI_OFF) + ks * 32);
            }
#pragma unroll
            for (int mf = 0; mf < 4; mf++)
#pragma unroll
                for (int nf = 0; nf < 2; nf++) {
                    mma16816(acc[mf][nf], ah[mf], bh[nf]);
                    mma16816(acc[mf][nf], ah[mf], bl[nf]);
                    mma16816(acc[mf][nf], al[mf], bh[nf]);
                }
        }
        __syncthreads();
    }

    // ---- epilogue
#pragma unroll
    for (int mf = 0; mf < 4; mf++) {
#pragma unroll
        for (int half = 0; half < 2; half++) {
            const int p = m0 + m0w + mf * 16 + g + half * 8;
            if (p >= Mtot) continue;
            const int im = p / HW;
            const int pp = p - im * HW;
            float* orow = dst + (size_t)im * dstride + (size_t)pp * COUT + co0;
#pragma unroll
            for (int nf = 0; nf < 2; nf++) {
                const int col = n0w + nf * 8 + tk;
                float v0 = acc[mf][nf][half * 2 + 0];
                float v1 = acc[mf][nf][half * 2 + 1];
                float2* d2 = (float2*)(orow + col);
                if (accum) {
                    float2 o = *d2;
                    v0 += o.x; v1 += o.y;
                } else if (bs) {
                    v0 += bs[co0 + col];
                    v1 += bs[co0 + col + 1];
                }
                d2->x = v0; d2->y = v1;
            }
        }
    }
}

// ---------------------------------------------------------------------------
// Weight transpose + bf16 split: w[k][co] (f32) -> whi/wlo[co][k] (bf16)
// ---------------------------------------------------------------------------
__global__ void wsplit(const float* __restrict__ w,
                       __nv_bfloat16* __restrict__ whi, __nv_bfloat16* __restrict__ wlo)
{
    __shared__ float tile[32][33];
    const int k0  = blockIdx.x * 32;
    const int co0 = blockIdx.y * 32;
    const int tx = threadIdx.x, ty = threadIdx.y;
#pragma unroll
    for (int i = 0; i < 4; i++)
        tile[ty + i * 8][tx] = w[(size_t)(k0 + ty + i * 8) * COUT + co0 + tx];
    __syncthreads();
#pragma unroll
    for (int i = 0; i < 4; i++) {
        const int co = co0 + ty + i * 8;
        const int k  = k0 + tx;
        const float v = tile[tx][ty + i * 8];
        const __nv_bfloat16 h = __float2bfloat16(v);
        whi[(size_t)co * KTOT + k] = h;
        wlo[(size_t)co * KTOT + k] = __float2bfloat16(v - __bfloat162float(h));
    }
}

// ---------------------------------------------------------------------------
// f32 -> bf16 hi/lo split (elementwise)
// ---------------------------------------------------------------------------
__global__ void xsplit(const float* __restrict__ in,
                       __nv_bfloat16* __restrict__ hi, __nv_bfloat16* __restrict__ lo,
                       size_t n)
{
    size_t i = (size_t)blockIdx.x * 256 + threadIdx.x;
    if (i >= n) return;
    const float v = in[i];
    const __nv_bfloat16 h = __float2bfloat16(v);
    hi[i] = h;
    lo[i] = __float2bfloat16(v - __bfloat162float(h));
}

// ---------------------------------------------------------------------------
// LSTM pointwise (+ emit hidden-state bf16 split); sums split-K partials
// ---------------------------------------------------------------------------
__device__ __forceinline__ float hsig(float x)
{
    return fminf(fmaxf(0.2f * x + 0.5f, 0.f), 1.f);
}

__global__ void lstm_point(const float* __restrict__ xg_t,
                           const float* __restrict__ xg2,   // null at t==0
                           float* __restrict__ cbuf,
                           float* __restrict__ h_out,
                           __nv_bfloat16* __restrict__ hhi,
                           __nv_bfloat16* __restrict__ hlo,
                           int first)
{
    int idx = blockIdx.x * 256 + threadIdx.x;
    if (idx >= (int)STATE_ELEMS) return;
    int b   = idx / (HW * Ff);
    int rem = idx - b * (HW * Ff);
    int pix = rem >> 8;
    int ch  = rem & 255;
    const float* gp = xg_t + (size_t)b * (Tt * HW * COUT) + (size_t)pix * COUT + ch;
    float gi = gp[0], gf = gp[256], gc = gp[512], go = gp[768];
    if (xg2) {
        const float* g2 = xg2 + ((size_t)b * HW + pix) * COUT + ch;
        gi += g2[0]; gf += g2[256]; gc += g2[512]; go += g2[768];
    }
    float i_ = hsig(gi);
    float f_ = hsig(gf);
    float cc = fmaxf(gc, 0.f);
    float o_ = hsig(go);
    float cp = first ? 0.f : cbuf[idx];
    float cn = f_ * cp + i_ * cc;
    cbuf[idx] = cn;
    float h = o_ * fmaxf(cn, 0.f);
    size_t oidx = (size_t)b * (Tt * HW * Ff) + rem;
    h_out[oidx] = h;
    __nv_bfloat16 hb = __float2bfloat16(h);
    hhi[oidx] = hb;
    hlo[oidx] = __float2bfloat16(h - __bfloat162float(hb));
}

// ---------------------------------------------------------------------------
// Instance norm
// ---------------------------------------------------------------------------
__global__ void inorm_stats(const float* __restrict__ seq, float2* __restrict__ stats)
{
    int b  = blockIdx.x >> 8;
    int ch = blockIdx.x & 255;
    const float* base = seq + (size_t)b * Tt * HW * Ff + ch;
    float s = 0.f, s2 = 0.f;
    for (int e = threadIdx.x; e < Tt * HW; e += 256) {
        float v = base[(size_t)e * Ff];
        s += v; s2 += v * v;
    }
    __shared__ float rs[256], rq[256];
    rs[threadIdx.x] = s;  rq[threadIdx.x] = s2;
    __syncthreads();
    for (int st = 128; st > 0; st >>= 1) {
        if (threadIdx.x < st) {
            rs[threadIdx.x] += rs[threadIdx.x + st];
            rq[threadIdx.x] += rq[threadIdx.x + st];
        }
        __syncthreads();
    }
    if (threadIdx.x == 0) {
        const float inv = 1.f / (float)(Tt * HW);
        float mu  = rs[0] * inv;
        float var = rq[0] * inv - mu * mu;
        stats[blockIdx.x] = make_float2(mu, rsqrtf(var + 1e-3f));
    }
}

__global__ void inorm_apply(const float* __restrict__ in,
                            const float2* __restrict__ stats,
                            const float* __restrict__ gamma,
                            const float* __restrict__ beta,
                            float* __restrict__ out,
                            __nv_bfloat16* __restrict__ shi,
                            __nv_bfloat16* __restrict__ slo)
{
    size_t idx = (size_t)blockIdx.x * 256 + threadIdx.x;
    if (idx >= SEQ_ELEMS) return;
    int ch = (int)(idx & 255);
    int b  = (int)(idx / ((size_t)Tt * HW * Ff));
    float2 st = stats[b * 256 + ch];
    float v = gamma[ch] * (in[idx] - st.x) * st.y + beta[ch];
    out[idx] = v;
    if (shi) {
        __nv_bfloat16 h = __float2bfloat16(v);
        shi[idx] = h;
        slo[idx] = __float2bfloat16(v - __bfloat162float(h));
    }
}

__global__ void copy_states(const float* __restrict__ seq2,
                            const float* __restrict__ cbuf,
                            float* __restrict__ h2, float* __restrict__ c2)
{
    int idx = blockIdx.x * 256 + threadIdx.x;
    if (idx >= (int)STATE_ELEMS) return;
    int b   = idx / (HW * Ff);
    int rem = idx - b * (HW * Ff);
    h2[idx] = seq2[(size_t)b * Tt * HW * Ff + (size_t)(Tt - 1) * HW * Ff + rem];
    c2[idx] = cbuf[idx];
}

// ---------------------------------------------------------------------------
// Orchestration
// ---------------------------------------------------------------------------
extern "C" void kernel_launch(void* const* d_in, const int* /*in_sizes*/, int /*n_in*/,
                              void* d_out, int /*out_size*/)
{
    const float* x   = (const float*)d_in[0];
    const float* k1  = (const float*)d_in[1];
    const float* rk1 = (const float*)d_in[2];
    const float* b1  = (const float*)d_in[3];
    const float* g1  = (const float*)d_in[4];
    const float* bt1 = (const float*)d_in[5];
    const float* k2  = (const float*)d_in[6];
    const float* rk2 = (const float*)d_in[7];
    const float* b2  = (const float*)d_in[8];
    const float* g2  = (const float*)d_in[9];
    const float* bt2 = (const float*)d_in[10];

    float* out    = (float*)d_out;
    float* out_h2 = out + SEQ_ELEMS;
    float* out_c2 = out_h2 + STATE_ELEMS;

    float *xg, *xg2, *seq1, *seq2, *cbuf;
    float2* stats;
    __nv_bfloat16 *ahi, *alo, *hhi, *hlo, *whi, *wlo;
    cudaGetSymbolAddress((void**)&xg,    g_xg);
    cudaGetSymbolAddress((void**)&xg2,   g_xg2);
    cudaGetSymbolAddress((void**)&seq1,  g_seq1);
    cudaGetSymbolAddress((void**)&seq2,  g_seq2);
    cudaGetSymbolAddress((void**)&cbuf,  g_c);
    cudaGetSymbolAddress((void**)&stats, g_stats);
    cudaGetSymbolAddress((void**)&ahi,   g_ahi);
    cudaGetSymbolAddress((void**)&alo,   g_alo);
    cudaGetSymbolAddress((void**)&hhi,   g_hhi);
    cudaGetSymbolAddress((void**)&hlo,   g_hlo);
    cudaGetSymbolAddress((void**)&whi,   g_whi);
    cudaGetSymbolAddress((void**)&wlo,   g_wlo);

    cudaFuncSetAttribute(conv_mma, cudaFuncAttributeMaxDynamicSharedMemorySize, SMEM_TOT);

    const dim3 wgrid(KTOT / 32, COUT / 32);
    const dim3 wblk(32, 8);
    wsplit<<<wgrid, wblk>>>(k1,  whi + 0 * W_ELEMS, wlo + 0 * W_ELEMS);
    wsplit<<<wgrid, wblk>>>(rk1, whi + 1 * W_ELEMS, wlo + 1 * W_ELEMS);
    wsplit<<<wgrid, wblk>>>(k2,  whi + 2 * W_ELEMS, wlo + 2 * W_ELEMS);
    wsplit<<<wgrid, wblk>>>(rk2, whi + 3 * W_ELEMS, wlo + 3 * W_ELEMS);

    const int sblocks = (int)((SEQ_ELEMS + 255) / 256);
    xsplit<<<sblocks, 256>>>(x, ahi, alo, SEQ_ELEMS);

    const int Min  = Bb * Tt * HW;                      // 21504
    const int Mrec = Bb * HW;                           // 1344
    const dim3 igrid(Min / MT, COUT / NT, 1);           // (168, 16, 1)
    const dim3 rgrid((Mrec + MT - 1) / MT, COUT / NT, 2); // (11, 16, 2)
    const int pblocks = (int)((STATE_ELEMS + 255) / 256);
    const size_t XSTR = (size_t)Tt * HW * COUT;
    const size_t X2STR = (size_t)HW * COUT;

    // ---------------- Layer 1 ----------------
    conv_mma<<<igrid, 256, SMEM_TOT>>>(
        ahi, alo, (size_t)HW * CIN, whi + 0 * W_ELEMS, wlo + 0 * W_ELEMS,
        b1, xg, (size_t)HW * COUT, nullptr, 0, Min);

    for (int t = 0; t < Tt; ++t) {
        if (t > 0)
            conv_mma<<<rgrid, 256, SMEM_TOT>>>(
                hhi + (size_t)(t - 1) * HW * Ff, hlo + (size_t)(t - 1) * HW * Ff,
                (size_t)Tt * HW * Ff,
                whi + 1 * W_ELEMS, wlo + 1 * W_ELEMS, nullptr,
                xg + (size_t)t * HW * COUT, XSTR, xg2, X2STR, Mrec);
        lstm_point<<<pblocks, 256>>>(xg + (size_t)t * HW * COUT,
                                     (t > 0) ? xg2 : nullptr, cbuf,
                                     seq1 + (size_t)t * HW * Ff,
                                     hhi + (size_t)t * HW * Ff,
                                     hlo + (size_t)t * HW * Ff, t == 0);
    }
    inorm_stats<<<Bb * Ff, 256>>>(seq1, stats);
    inorm_apply<<<sblocks, 256>>>(seq1, stats, g1, bt1, seq1, ahi, alo);

    // ---------------- Layer 2 ----------------
    conv_mma<<<igrid, 256, SMEM_TOT>>>(
        ahi, alo, (size_t)HW * CIN, whi + 2 * W_ELEMS, wlo + 2 * W_ELEMS,
        b2, xg, (size_t)HW * COUT, nullptr, 0, Min);

    for (int t = 0; t < Tt; ++t) {
        if (t > 0)
            conv_mma<<<rgrid, 256, SMEM_TOT>>>(
                hhi + (size_t)(t - 1) * HW * Ff, hlo + (size_t)(t - 1) * HW * Ff,
                (size_t)Tt * HW * Ff,
                whi + 3 * W_ELEMS, wlo + 3 * W_ELEMS, nullptr,
                xg + (size_t)t * HW * COUT, XSTR, xg2, X2STR, Mrec);
        lstm_point<<<pblocks, 256>>>(xg + (size_t)t * HW * COUT,
                                     (t > 0) ? xg2 : nullptr, cbuf,
                                     seq2 + (size_t)t * HW * Ff,
                                     hhi + (size_t)t * HW * Ff,
                                     hlo + (size_t)t * HW * Ff, t == 0);
    }

    copy_states<<<pblocks, 256>>>(seq2, cbuf, out_h2, out_c2);
    inorm_stats<<<Bb * Ff, 256>>>(seq2, stats);
    inorm_apply<<<sblocks, 256>>>(seq2, stats, g2, bt2, out, nullptr, nullptr);
}